// round 1
// baseline (speedup 1.0000x reference)
#include <cuda_runtime.h>
#include <math.h>

// Problem constants
#define LSEQ 131072
#define NB 4            // batch (== heads)
#define NC 64           // channels
#define TT 126          // valid columns per tile
#define THALO 128       // TT + 2 halo
#define NTILES ((LSEQ + TT - 1) / TT)   // 1041
#define K1BLKS 148
#define PART_STRIDE 4224                // 64*64 S + 64 qq + 64 kk

// Scratch (no cudaMalloc allowed)
__device__ float g_part[NB * K1BLKS * PART_STRIDE];
__device__ float g_P[NB * NC * NC];

// ---------------------------------------------------------------------------
// Register-tiled 64xK GEMM helper.
// A: smem, layout A[k*68 + o]  (transposed weights, float4 along o)
// B: smem, layout B[k*132 + l] (row-major columns, float4 along l)
// C: smem, layout C[(o)*ldc + l], computes 4 o x 8 l per thread, 256 threads
// covers 64 x 128 outputs.
// ---------------------------------------------------------------------------
__device__ __forceinline__ void gemm64_smem(const float* __restrict__ A,
                                            const float* __restrict__ B,
                                            float* __restrict__ C,
                                            int ldc, int o0, int lB)
{
    float acc[4][8];
#pragma unroll
    for (int i = 0; i < 4; i++)
#pragma unroll
        for (int j = 0; j < 8; j++) acc[i][j] = 0.f;

#pragma unroll 8
    for (int k = 0; k < 64; k++) {
        float4 a  = *(const float4*)(A + k * 68 + o0);
        float4 b0 = *(const float4*)(B + k * 132 + lB);
        float4 b1 = *(const float4*)(B + k * 132 + lB + 4);
        float av[4] = {a.x, a.y, a.z, a.w};
        float bv[8] = {b0.x, b0.y, b0.z, b0.w, b1.x, b1.y, b1.z, b1.w};
#pragma unroll
        for (int i = 0; i < 4; i++)
#pragma unroll
            for (int j = 0; j < 8; j++) acc[i][j] = fmaf(av[i], bv[j], acc[i][j]);
    }
#pragma unroll
    for (int i = 0; i < 4; i++)
#pragma unroll
        for (int j = 0; j < 8; j++) C[(o0 + i) * ldc + lB + j] = acc[i][j];
}

// ---------------------------------------------------------------------------
// K1: per (b, block) accumulate partial Gram S = sum_l q k^T, and sum q^2,
// sum k^2 per channel. q = dwconv3(Wq @ x), k = dwconv3(Wk @ x).
// ---------------------------------------------------------------------------
__global__ __launch_bounds__(256, 1)
void k1_qk_gram(const float* __restrict__ x,
                const float* __restrict__ w_kv,
                const float* __restrict__ w_kv_dw,
                const float* __restrict__ w_q,
                const float* __restrict__ w_q_dw)
{
    extern __shared__ float sm[];
    float* xs  = sm;            // 64*132 = 8448
    float* ys  = xs + 8448;     // 64*133 = 8512
    float* qs  = ys + 8512;     // 128*64 = 8192  layout [l][c]
    float* ks  = qs + 8192;     // 8192
    float* wsq = ks + 8192;     // 64*68 = 4352   layout [k][o]
    float* wsk = wsq + 4352;    // 4352
    float* wdq = wsk + 4352;    // 192
    float* wdk = wdq + 192;     // 192

    const int tid = threadIdx.x;
    const int b = blockIdx.y;

    // Load + transpose the 1x1 weights
    for (int idx = tid; idx < 4096; idx += 256) {
        int o = idx >> 6, k = idx & 63;
        wsq[k * 68 + o] = w_q[idx];       // Wq[o][k]
        wsk[k * 68 + o] = w_kv[idx];      // Wk = rows 0..63 of w_kv
    }
    for (int idx = tid; idx < 192; idx += 256) {
        wdq[idx] = w_q_dw[idx];
        wdk[idx] = w_kv_dw[idx];          // rows 0..63
    }
    __syncthreads();

    float accS[16];
#pragma unroll
    for (int i = 0; i < 16; i++) accS[i] = 0.f;
    float accqq = 0.f, acckk = 0.f;

    const int cg = tid & 15, dg = tid >> 4;
    const int c0 = cg * 4, d0 = dg * 4;
    const int o0 = (tid >> 4) * 4, lB = (tid & 15) * 8;

    for (int t = blockIdx.x; t < NTILES; t += K1BLKS) {
        const long l0 = (long)t * TT - 1;

        // Load x tile (zero-padded halo)
        for (int idx = tid; idx < NC * THALO; idx += 256) {
            int c = idx >> 7, li = idx & 127;
            long gl = l0 + li;
            float v = 0.f;
            if (gl >= 0 && gl < LSEQ)
                v = x[(long)(b * NC + c) * LSEQ + gl];
            xs[c * 132 + li] = v;
        }
        __syncthreads();

        // y = Wq @ x  (64 x 128 cols)
        gemm64_smem(wsq, xs, ys, 133, o0, lB);
        __syncthreads();

        // q = dwconv3(y) -> qs[l][c], l in [0, TT)
        for (int idx = tid; idx < TT * NC; idx += 256) {
            int c = idx & 63, l = idx >> 6;
            const float* yr = ys + c * 133 + l;
            qs[l * 64 + c] = wdq[c * 3] * yr[0] + wdq[c * 3 + 1] * yr[1]
                           + wdq[c * 3 + 2] * yr[2];
        }
        __syncthreads();

        // y = Wk @ x
        gemm64_smem(wsk, xs, ys, 133, o0, lB);
        __syncthreads();

        // k = dwconv3(y) -> ks[l][c]
        for (int idx = tid; idx < TT * NC; idx += 256) {
            int c = idx & 63, l = idx >> 6;
            const float* yr = ys + c * 133 + l;
            ks[l * 64 + c] = wdk[c * 3] * yr[0] + wdk[c * 3 + 1] * yr[1]
                           + wdk[c * 3 + 2] * yr[2];
        }
        __syncthreads();

        // per-channel squared sums (warps 0-3)
        if (tid < 64) {
            float s = 0.f;
            for (int l = 0; l < TT; l++) { float v = qs[l * 64 + tid]; s = fmaf(v, v, s); }
            accqq += s;
        } else if (tid < 128) {
            int c = tid - 64;
            float s = 0.f;
            for (int l = 0; l < TT; l++) { float v = ks[l * 64 + c]; s = fmaf(v, v, s); }
            acckk += s;
        }

        // Gram: S[c0..c0+3][d0..d0+3] += q k^T
#pragma unroll 2
        for (int l = 0; l < TT; l++) {
            float4 qv = *(const float4*)(qs + l * 64 + c0);
            float4 kv = *(const float4*)(ks + l * 64 + d0);
            float qa[4] = {qv.x, qv.y, qv.z, qv.w};
            float ka[4] = {kv.x, kv.y, kv.z, kv.w};
#pragma unroll
            for (int i = 0; i < 4; i++)
#pragma unroll
                for (int j = 0; j < 4; j++)
                    accS[i * 4 + j] = fmaf(qa[i], ka[j], accS[i * 4 + j]);
        }
        __syncthreads();
    }

    // Write partials (fixed order -> deterministic)
    float* pb = g_part + ((long)b * K1BLKS + blockIdx.x) * PART_STRIDE;
#pragma unroll
    for (int i = 0; i < 4; i++)
#pragma unroll
        for (int j = 0; j < 4; j++)
            pb[(c0 + i) * 64 + d0 + j] = accS[i * 4 + j];
    if (tid < 64) pb[4096 + tid] = accqq;
    else if (tid < 128) pb[4160 + (tid - 64)] = acckk;
}

// ---------------------------------------------------------------------------
// K2: reduce partials, l2-normalize, temperature, softmax over d,
// then P = W_proj @ attn. One block per batch.
// ---------------------------------------------------------------------------
__global__ __launch_bounds__(256)
void k2_softmax(const float* __restrict__ w_proj,
                const float* __restrict__ temperature)
{
    __shared__ float S[4096];
    __shared__ float nq[64];
    __shared__ float nk[64];
    __shared__ float attn[4096];

    const int b = blockIdx.x;
    const int tid = threadIdx.x;

    for (int idx = tid; idx < PART_STRIDE; idx += 256) {
        const float* p = g_part + (long)b * K1BLKS * PART_STRIDE + idx;
        float s = 0.f;
        for (int blk = 0; blk < K1BLKS; blk++) s += p[(long)blk * PART_STRIDE];
        if (idx < 4096) S[idx] = s;
        else if (idx < 4160) nq[idx - 4096] = fmaxf(sqrtf(s), 1e-12f);
        else nk[idx - 4160] = fmaxf(sqrtf(s), 1e-12f);
    }
    __syncthreads();

    const float tempv = temperature[b];
    for (int idx = tid; idx < 4096; idx += 256) {
        int c = idx >> 6, d = idx & 63;
        attn[idx] = tempv * S[idx] / (nq[c] * nk[d]);
    }
    __syncthreads();

    if (tid < 64) {
        const int c = tid;
        float m = -1e30f;
        for (int d = 0; d < 64; d++) m = fmaxf(m, attn[c * 64 + d]);
        float s = 0.f;
        for (int d = 0; d < 64; d++) {
            float e = expf(attn[c * 64 + d] - m);
            attn[c * 64 + d] = e;
            s += e;
        }
        float inv = 1.f / s;
        for (int d = 0; d < 64; d++) attn[c * 64 + d] *= inv;
    }
    __syncthreads();

    // P = W_proj @ attn
    for (int idx = tid; idx < 4096; idx += 256) {
        int o = idx >> 6, d = idx & 63;
        float s = 0.f;
        for (int c = 0; c < 64; c++)
            s = fmaf(w_proj[o * 64 + c], attn[c * 64 + d], s);
        g_P[b * 4096 + idx] = s;
    }
}

// ---------------------------------------------------------------------------
// K3: out = P @ dwconv3(Wv @ x), streamed per tile.
// ---------------------------------------------------------------------------
__global__ __launch_bounds__(256, 2)
void k3_out(const float* __restrict__ x,
            const float* __restrict__ w_kv,
            const float* __restrict__ w_kv_dw,
            float* __restrict__ out)
{
    extern __shared__ float sm[];
    float* xs  = sm;            // 8448 (vs aliases this after yv is done)
    float* yv  = xs + 8448;     // 64*132 = 8448
    float* wsv = yv + 8448;     // 4352  [k][o]
    float* ps  = wsv + 4352;    // 4352  [c][o]  (P transposed)
    float* wdv = ps + 4352;     // 192
    float* vs  = xs;            // alias

    const int tid = threadIdx.x;
    const int b = blockIdx.y;
    const int t = blockIdx.x;

    for (int idx = tid; idx < 4096; idx += 256) {
        int o = idx >> 6, k = idx & 63;
        wsv[k * 68 + o] = w_kv[(64 + o) * 64 + k];   // Wv = rows 64..127
        ps[k * 68 + o]  = g_P[b * 4096 + idx];       // ps[c][o] = P[o][c]
    }
    for (int idx = tid; idx < 192; idx += 256)
        wdv[idx] = w_kv_dw[192 + idx];               // rows 64..127
    // no sync needed yet: xs load below doesn't touch these
    const long l0 = (long)t * TT - 1;
    for (int idx = tid; idx < NC * THALO; idx += 256) {
        int c = idx >> 7, li = idx & 127;
        long gl = l0 + li;
        float v = 0.f;
        if (gl >= 0 && gl < LSEQ)
            v = x[(long)(b * NC + c) * LSEQ + gl];
        xs[c * 132 + li] = v;
    }
    __syncthreads();

    const int o0 = (tid >> 4) * 4, lB = (tid & 15) * 8;

    // yv = Wv @ x
    gemm64_smem(wsv, xs, yv, 132, o0, lB);
    __syncthreads();

    // v = dwconv3(yv) -> vs[c][l] (aliases xs; yv read, xs dead)
    for (int idx = tid; idx < NC * THALO; idx += 256) {
        int c = idx >> 7, l = idx & 127;
        if (l < TT) {
            const float* yr = yv + c * 132 + l;
            vs[c * 132 + l] = wdv[c * 3] * yr[0] + wdv[c * 3 + 1] * yr[1]
                            + wdv[c * 3 + 2] * yr[2];
        }
    }
    __syncthreads();

    // out tile = P @ v   (contract over c)
    {
        float acc[4][8];
#pragma unroll
        for (int i = 0; i < 4; i++)
#pragma unroll
            for (int j = 0; j < 8; j++) acc[i][j] = 0.f;

#pragma unroll 8
        for (int c = 0; c < 64; c++) {
            float4 a  = *(const float4*)(ps + c * 68 + o0);
            float4 b0 = *(const float4*)(vs + c * 132 + lB);
            float4 b1 = *(const float4*)(vs + c * 132 + lB + 4);
            float av[4] = {a.x, a.y, a.z, a.w};
            float bv[8] = {b0.x, b0.y, b0.z, b0.w, b1.x, b1.y, b1.z, b1.w};
#pragma unroll
            for (int i = 0; i < 4; i++)
#pragma unroll
                for (int j = 0; j < 8; j++) acc[i][j] = fmaf(av[i], bv[j], acc[i][j]);
        }

#pragma unroll
        for (int i = 0; i < 4; i++) {
#pragma unroll
            for (int j = 0; j < 8; j++) {
                int l = lB + j;
                long gl = (long)t * TT + l;
                if (l < TT && gl < LSEQ)
                    out[(long)(b * NC + o0 + i) * LSEQ + gl] = acc[i][j];
            }
        }
    }
}

// ---------------------------------------------------------------------------
extern "C" void kernel_launch(void* const* d_in, const int* in_sizes, int n_in,
                              void* d_out, int out_size)
{
    const float* x           = (const float*)d_in[0];
    const float* w_kv        = (const float*)d_in[1];
    const float* w_kv_dw     = (const float*)d_in[2];
    const float* w_q         = (const float*)d_in[3];
    const float* w_q_dw      = (const float*)d_in[4];
    const float* w_proj      = (const float*)d_in[5];
    const float* temperature = (const float*)d_in[6];
    float* out = (float*)d_out;

    const int SM1 = 42432 * 4;   // 169728 B
    const int SM3 = 25792 * 4;   // 103168 B
    cudaFuncSetAttribute(k1_qk_gram, cudaFuncAttributeMaxDynamicSharedMemorySize, SM1);
    cudaFuncSetAttribute(k3_out,     cudaFuncAttributeMaxDynamicSharedMemorySize, SM3);

    k1_qk_gram<<<dim3(K1BLKS, NB), 256, SM1>>>(x, w_kv, w_kv_dw, w_q, w_q_dw);
    k2_softmax<<<NB, 256>>>(w_proj, temperature);
    k3_out<<<dim3(NTILES, NB), 256, SM3>>>(x, w_kv, w_kv_dw, out);
}